// round 14
// baseline (speedup 1.0000x reference)
#include <cuda_runtime.h>

// GaussianBlur v7 = v6 inner loops, re-tiled for occupancy + zero raggedness.
// depthwise 21x21 Gaussian (sigma=5), reflect pad 10, [32,3,512,512] fp32.
// Tile 128x32 outputs, 256 threads, 6 CTA/SM (reg cap 42, smem 18.5KB):
//   phase 1: VERTICAL 21-tap from gmem. 148 column-tasks -> one round.
//            28-register sliding window, 4 stages x 8 outputs; refills
//            front-batched 8 wide (MLP>=8). Dense coalesced column loads.
//   phase 2: HORIZONTAL 21-tap from smem: 8 warps x 4 iterations cover all
//            32 rows exactly (100% util). 6x LDS.128 conflict-free 4-output
//            windows, FFMA-imm, STG.128 dense.

#define W_ 512
#define H_ 512
#define NIMG 96
#define PAD 10

#define TX 128
#define TY 32
#define VCOLS   148                 // TX + 2*PAD  (= phase-1 task count)
#define VSTRIDE 148                 // floats per smem row (592B)
#define VWIN    (TY + 2 * PAD)      // 52 rows read per task
#define WNDW    28                  // phase-1 register window

// 1D separable weights (validated rel_err 3.4e-7): exp(-(d^2)/50)/12.089199128
#define KW_INIT const float KW[21] = { \
    0.01119473f, 0.01636989f, 0.02299883f, 0.03104516f, 0.04026340f, \
    0.05017128f, 0.06006594f, 0.06909227f, 0.07635877f, 0.08108053f, \
    0.08271847f, \
    0.08108053f, 0.07635877f, 0.06909227f, 0.06006594f, 0.05017128f, \
    0.04026340f, 0.03104516f, 0.02299883f, 0.01636989f, 0.01119473f }

__device__ __forceinline__ int reflect512(int i) {
    // jnp.pad mode="reflect": -k -> k, 511+k -> 511-k (single reflection)
    i = (i < 0) ? -i : i;
    return (i > 511) ? (1022 - i) : i;
}

// ---- Phase-1 task: vertical conv of one column, 32 output rows ------------
// 28-slot window, slot(row) = row % 28 (compile-time after unroll).
// Stage s: compute outputs 8s..8s+7 from rows 8s..8s+27, then refill the 8
// dead slots with rows 28+8s..35+8s (front-batched, independent loads).
template <bool INTERIOR>
__device__ __forceinline__ void vtask(const float* __restrict__ img,
                                      float* __restrict__ dst,
                                      int yb, int gx) {
    KW_INIT;
    const float* __restrict__ p =
        img + (size_t)(INTERIOR ? yb : 0) * W_ + gx;

    float v[WNDW];
    #pragma unroll
    for (int j = 0; j < WNDW; ++j)
        v[j] = INTERIOR ? p[j * W_]
                        : img[(size_t)reflect512(yb + j) * W_ + gx];

    #pragma unroll
    for (int s = 0; s < 4; ++s) {
        #pragma unroll
        for (int rr = 0; rr < 8; ++rr) {
            const int orow = 8 * s + rr;
            float a = 0.f;
            #pragma unroll
            for (int k = 0; k < 21; ++k)
                a = fmaf(KW[k], v[(orow + k) % WNDW], a);
            dst[orow * VSTRIDE] = a;           // conflict-free STS
        }
        if (s < 3) {
            #pragma unroll
            for (int j = 0; j < 8; ++j) {
                const int row = WNDW + 8 * s + j;
                v[row % WNDW] = INTERIOR
                    ? p[row * W_]
                    : img[(size_t)reflect512(yb + row) * W_ + gx];
            }
        }
    }
}

// Cold path (y-border tiles only): keep out of the hot instruction stream.
__device__ __noinline__ void vtask_border(const float* __restrict__ img,
                                          float* __restrict__ dst,
                                          int yb, int gx) {
    vtask<false>(img, dst, yb, gx);
}

__global__ __launch_bounds__(256, 6)
void blur_v7(const float* __restrict__ in, float* __restrict__ out) {
    KW_INIT;
    __shared__ __align__(16) float Vs[TY * VSTRIDE];   // 18944 B

    const int n   = blockIdx.z;
    const int x0  = blockIdx.x * TX;
    const int y0  = blockIdx.y * TY;
    const int tid = threadIdx.x;

    const float* __restrict__ img = in + (size_t)n * (H_ * W_);

    // ---- Phase 1: vertical conv, gmem -> Vs. One task per thread, 1 round.
    if (tid < VCOLS) {
        const int gx = reflect512(x0 - PAD + tid);
        const int yb = y0 - PAD;
        float* dst = Vs + tid;
        if (yb >= 0 && yb + VWIN <= H_)
            vtask<true>(img, dst, yb, gx);
        else
            vtask_border(img, dst, yb, gx);
    }
    __syncthreads();

    // ---- Phase 2: horizontal conv, Vs -> gmem. 8 warps x 4 iters = 32 rows.
    // Lane g -> outputs [4g..4g+3] from window Vs[r][4g..4g+23]:
    // 6x LDS.128 at 16B-stride starts (conflict-free phases), STG.128 dense.
    float* __restrict__ outimg = out + (size_t)n * (H_ * W_);
    const int g  = tid & 31;
    const int wp = tid >> 5;       // 0..7

    #pragma unroll
    for (int i = 0; i < 4; ++i) {
        const int r = wp + 8 * i;
        const float* __restrict__ src = Vs + r * VSTRIDE + 4 * g;

        float wv[24];
        #pragma unroll
        for (int j = 0; j < 6; ++j) {
            float4 t = *reinterpret_cast<const float4*>(src + 4 * j);
            wv[4 * j + 0] = t.x; wv[4 * j + 1] = t.y;
            wv[4 * j + 2] = t.z; wv[4 * j + 3] = t.w;
        }

        float h0 = 0.f, h1 = 0.f, h2 = 0.f, h3 = 0.f;
        #pragma unroll
        for (int k = 0; k < 21; ++k) {
            const float w = KW[k];
            h0 = fmaf(w, wv[k + 0], h0);
            h1 = fmaf(w, wv[k + 1], h1);
            h2 = fmaf(w, wv[k + 2], h2);
            h3 = fmaf(w, wv[k + 3], h3);
        }
        *reinterpret_cast<float4*>(outimg + (size_t)(y0 + r) * W_ + x0 + 4 * g)
            = make_float4(h0, h1, h2, h3);
    }
}

extern "C" void kernel_launch(void* const* d_in, const int* in_sizes, int n_in,
                              void* d_out, int out_size) {
    const float* x = (const float*)d_in[0];
    float* out = (float*)d_out;
    (void)in_sizes; (void)n_in; (void)out_size;

    // 4 x-tiles, 16 y-tiles, 96 images = 6144 blocks of 256 threads
    blur_v7<<<dim3(W_ / TX, H_ / TY, NIMG), 256>>>(x, out);
}